// round 14
// baseline (speedup 1.0000x reference)
#include <cuda_runtime.h>
#include <cuda_fp16.h>
#include <cstdint>

// ---------------- problem constants ----------------
#define N_ATOMS_MAX 131072
#define DQ      256
#define H1      512
#define NTYPE   4
#define TILE_M  128
#define MAX_TILES (N_ATOMS_MAX / TILE_M + NTYPE)  // 1028
#define BLOCK   256

// ---------------- smem layout (byte offsets) ----------------
// A: [blk16 0..7][grp 0..15][lane 0..31] x 16 B   (fragment-order, lane^(grp&7) swizzle)
// B: none — B fragments are loaded LDG->register from L2-resident g_W0H
#define B_OFF_F    0                    // s_F[128] floats
#define B_OFF_IDX  512                  // s_idx[128] ints
#define B_OFF_B0   1024                 // s_b0[512] floats
#define B_OFF_W1   3072                 // s_w1[512] floats
#define B_OFF_A    5120                 // 64 KB
#define SMEM_BYTES (B_OFF_A + 65536)    // 70656 B -> 2 CTAs / SM

// ---------------- device scratch ----------------
__device__ __half g_W0H[NTYPE * H1 * DQ];      // W0^T fp16, (chunk,group)-sliced fragment order
__device__ int    g_idx[NTYPE * N_ATOMS_MAX];  // per-type regions
__device__ int    g_cnt[NTYPE];
__device__ float  g_warm_sink;

// ---------------- helpers ----------------
static __device__ __forceinline__ float tanh_fast(float x) {
    float y;
    asm("tanh.approx.f32 %0, %1;" : "=f"(y) : "f"(x));
    return y;
}
static __device__ __forceinline__ uint32_t pack_h2(float lo, float hi) {
    uint32_t r;
    asm("cvt.rn.f16x2.f32 %0, %1, %2;" : "=r"(r) : "f"(hi), "f"(lo));
    return r;
}
static __device__ __forceinline__ void mma_f16(float* c, uint32_t a0, uint32_t a1,
                                               uint32_t a2, uint32_t a3,
                                               uint32_t b0, uint32_t b1) {
    asm volatile(
        "mma.sync.aligned.m16n8k16.row.col.f32.f16.f16.f32 "
        "{%0,%1,%2,%3}, {%4,%5,%6,%7}, {%8,%9}, {%0,%1,%2,%3};"
        : "+f"(c[0]), "+f"(c[1]), "+f"(c[2]), "+f"(c[3])
        : "r"(a0), "r"(a1), "r"(a2), "r"(a3), "r"(b0), "r"(b1));
}

// ---------------- prep 1: init counters + W0 transpose into sliced fragment-order ----
__global__ void k_init_transpose(const float* __restrict__ W0) {
    if (blockIdx.x == 0 && threadIdx.x < NTYPE) g_cnt[threadIdx.x] = 0;
    __shared__ float tile[32][33];
    const int bid = blockIdx.x;
    const int kx = bid & 7, jy = (bid >> 3) & 15, t = bid >> 7;
    const int k0 = kx * 32, j0 = jy * 32;
    const int x = threadIdx.x & 31, y0 = threadIdx.x >> 5;   // 32 x 8
#pragma unroll
    for (int dy = 0; dy < 32; dy += 8) {
        int k = k0 + y0 + dy, j = j0 + x;
        tile[y0 + dy][x] = W0[((size_t)t * DQ + k) * H1 + j];
    }
    __syncthreads();
#pragma unroll
    for (int dy = 0; dy < 32; dy += 8) {
        const int j = j0 + y0 + dy;      // H1 index (n)
        const int k = k0 + x;            // DQ index
        const int ng   = j >> 7;         // 128-col n-group
        const int blkn = (j >> 4) & 7;   // 16-col block within group
        const int gn   = blkn >> 1;      // warpN that reads this block
        const int bb   = blkn & 1;
        const int rb   = j & 15;
        const int jj = rb >> 3, g = rb & 7;
        const int kc = k >> 6;           // 64-k chunk
        const int p  = (k >> 4) & 3;     // k16 step within chunk
        const int ki = k & 15;
        const int tg = (ki >> 1) & 3;
        const int posq = ((ki >> 3) << 1) | (ki & 1);
        const int lane = g * 4 + tg;     // no swizzle: read by LDG
        const int ci = ng * 4 + kc;
        const int halfIdx = (((((ci * 4 + gn) * 2 + bb) * 4 + p) * 32 + lane) << 3) + jj * 4 + posq;
        g_W0H[(size_t)t * (H1 * DQ) + halfIdx] = __float2half_rn(tile[x][y0 + dy]);
    }
}

// ---------------- prep 2: scatter with block-aggregated atomics ----------------
__global__ void k_scatter(const int* __restrict__ Z, int n) {
    __shared__ int wcnt[8][NTYPE];
    __shared__ int wbase[8][NTYPE];
    __shared__ int blkbase[NTYPE];
    const int i = blockIdx.x * blockDim.x + threadIdx.x;
    const int lane = threadIdx.x & 31, w = threadIdx.x >> 5;
    int z = -1, rank = 0;
    if (i < n) {
        z = Z[i];
#pragma unroll
        for (int t = 0; t < NTYPE; t++) {
            unsigned m = __ballot_sync(0xffffffffu, z == t);
            if (lane == 0) wcnt[w][t] = __popc(m);
            if (z == t) rank = __popc(m & ((1u << lane) - 1u));
        }
    } else if (lane == 0) {
#pragma unroll
        for (int t = 0; t < NTYPE; t++) wcnt[w][t] = 0;
    }
    __syncthreads();
    if (threadIdx.x < NTYPE) {
        const int t = threadIdx.x;
        int s = 0;
#pragma unroll
        for (int w2 = 0; w2 < 8; w2++) { wbase[w2][t] = s; s += wcnt[w2][t]; }
        blkbase[t] = atomicAdd(&g_cnt[t], s);
    }
    __syncthreads();
    if (z >= 0) g_idx[z * N_ATOMS_MAX + blkbase[z] + wbase[w][z] + rank] = i;
}

// ---------------- prep 3: warm g_W0H into L2 (also keeps k_gemm as 4th launch) ----
__global__ void k_warm() {
    const float2* p = (const float2*)g_W0H;   // 512 KB = 65536 float2
    float acc = 0.0f;
    const int i0 = blockIdx.x * 256 + threadIdx.x;
    for (int i = i0; i < 65536; i += 128 * 256) {
        float2 v = p[i];
        acc += v.x + v.y;
    }
    if (acc == 12345.678f) g_warm_sink = acc;  // never true; defeats DCE
}

// ---------------- main fused GEMM + tanh + dot kernel ----------------
__global__ void __launch_bounds__(BLOCK, 2)
k_gemm(const float* __restrict__ q, const float* __restrict__ b0,
       const float* __restrict__ W1, const float* __restrict__ b1v,
       float* __restrict__ out) {
    extern __shared__ char smem[];
    const int tid = threadIdx.x;
    const int wid = tid >> 5, lane = tid & 31;
    const int g = lane >> 2, tig = lane & 3;
    const int warpM = wid & 1, warpN = wid >> 1;   // 2M x 4N; warp tile 64 rows x 32 cols
    // ---- tile table from g_cnt ----
    const int c0 = g_cnt[0], c1 = g_cnt[1], c2 = g_cnt[2], c3 = g_cnt[3];
    const int n0 = (c0 + TILE_M - 1) >> 7;
    const int n1 = (c1 + TILE_M - 1) >> 7;
    const int n2 = (c2 + TILE_M - 1) >> 7;
    const int bid = blockIdx.x;
    int t, lt, cnt;
    if (bid < n0)                { t = 0; lt = bid;                cnt = c0; }
    else if (bid < n0 + n1)      { t = 1; lt = bid - n0;           cnt = c1; }
    else if (bid < n0 + n1 + n2) { t = 2; lt = bid - n0 - n1;      cnt = c2; }
    else { t = 3; lt = bid - n0 - n1 - n2; cnt = c3;
           if (lt >= (c3 + TILE_M - 1) >> 7) return; }
    const int row0 = lt * TILE_M;

    float*  s_F   = (float*)(smem + B_OFF_F);
    int*    s_idx = (int*)(smem + B_OFF_IDX);
    float*  s_b0  = (float*)(smem + B_OFF_B0);
    float*  s_w1  = (float*)(smem + B_OFF_W1);
    char*   s_A   = smem + B_OFF_A;

    const __half* w0h = g_W0H + (size_t)t * (H1 * DQ);

    if (tid < TILE_M) {
        int r = row0 + tid;
        s_idx[tid] = g_idx[t * N_ATOMS_MAX + (r < cnt ? r : row0)];
        s_F[tid] = 0.0f;
    }
#pragma unroll
    for (int o = 0; o < 2; o++) {
        const int c = o * BLOCK + tid;
        s_b0[c] = b0[t * H1 + c];
        s_w1[c] = W1[t * H1 + c];
    }
    __syncthreads();   // s_idx visible

    // A gather: 128 rows x 16 k16-groups = 2048 tasks (8/thread)
#pragma unroll
    for (int o = 0; o < 8; o++) {
        const int lin = o * BLOCK + tid;
        const int grp = lin & 15, row = lin >> 4;
        const float* src = q + (size_t)s_idx[row] * DQ + grp * 16;
        float v[16];
#pragma unroll
        for (int s = 0; s < 4; s++) {
            const float4 f4 = *(const float4*)(src + s * 4);
            v[s * 4 + 0] = f4.x; v[s * 4 + 1] = f4.y;
            v[s * 4 + 2] = f4.z; v[s * 4 + 3] = f4.w;
        }
        const int blk = row >> 4, half = (row >> 3) & 1, gg = row & 7;
        char* dbase = s_A + ((blk * 16 + grp) << 9) + half * 8;
        const int sw = grp & 7;
#pragma unroll
        for (int tt = 0; tt < 4; tt++) {
            uint2 pr;
            pr.x = pack_h2(v[tt * 2],     v[tt * 2 + 1]);
            pr.y = pack_h2(v[tt * 2 + 8], v[tt * 2 + 9]);
            *(uint2*)(dbase + (((gg * 4 + tt) ^ sw) << 4)) = pr;
        }
    }
    __syncthreads();   // A tile visible to all warps; mainloop is barrier-free

    const float b1s = b1v[0];
    const char* As_base = s_A + warpM * 64 * 512;      // + (kc*4 + i*16 + p)*512 + swA
    const char* Bg_lane = (const char*)w0h + warpN * 4096 + lane * 16;

    // deferred per-row partials, accumulated across all 4 n-groups
    float fa[4][2];
#pragma unroll
    for (int i = 0; i < 4; i++) { fa[i][0] = 0.0f; fa[i][1] = 0.0f; }

    // B 3-buffer ring, 2-step lookahead; all indices compile-time (full unroll)
    uint4 Bb[3][2];
    {
        const char* B0 = Bg_lane;                 // ss=0: ng0,kc0,p0
        const char* B1 = Bg_lane + 512;           // ss=1: p1
        Bb[0][0] = *(const uint4*)(B0); Bb[0][1] = *(const uint4*)(B0 + 2048);
        Bb[1][0] = *(const uint4*)(B1); Bb[1][1] = *(const uint4*)(B1 + 2048);
    }

#pragma unroll
    for (int ng = 0; ng < 4; ng++) {            // 128-col n-groups
        float acc[4][4][4];                     // [i: 16-row blk][f = bb*2+jj][c]
#pragma unroll
        for (int i = 0; i < 4; i++)
#pragma unroll
            for (int f = 0; f < 4; f++)
#pragma unroll
                for (int c = 0; c < 4; c++) acc[i][f][c] = 0.0f;

#pragma unroll
        for (int s = 0; s < 16; s++) {
            const int ss = ng * 16 + s;
            const int cb = ss % 3;
            // prefetch B for ss+2
            if (ss + 2 < 64) {
                const int s2 = ss + 2;
                const char* Bn = Bg_lane + (s2 >> 4) * 65536 + ((s2 >> 2) & 3) * 16384 + (s2 & 3) * 512;
                Bb[s2 % 3][0] = *(const uint4*)(Bn);
                Bb[s2 % 3][1] = *(const uint4*)(Bn + 2048);
            }
            // A fragments for this step (smem, short latency; ptxas hoists freely)
            const int kcn = s >> 2, pn = s & 3;
            const int swA = (lane ^ (((kcn & 1) << 2) | pn)) << 4;
            uint4 A[4];
#pragma unroll
            for (int i = 0; i < 4; i++)
                A[i] = *(const uint4*)(As_base + (kcn * 4 + i * 16 + pn) * 512 + swA);
            // A uint4: {a0, a2, a1, a3}; B uint4: {b0_j0, b1_j0, b0_j1, b1_j1}
#pragma unroll
            for (int i = 0; i < 4; i++) {
                mma_f16(acc[i][0], A[i].x, A[i].z, A[i].y, A[i].w, Bb[cb][0].x, Bb[cb][0].y);
                mma_f16(acc[i][1], A[i].x, A[i].z, A[i].y, A[i].w, Bb[cb][0].z, Bb[cb][0].w);
                mma_f16(acc[i][2], A[i].x, A[i].z, A[i].y, A[i].w, Bb[cb][1].x, Bb[cb][1].y);
                mma_f16(acc[i][3], A[i].x, A[i].z, A[i].y, A[i].w, Bb[cb][1].z, Bb[cb][1].w);
            }
        }

        // ---- per-ng: tanh(h + b0) * W1 into persistent fa (reduce deferred) ----
#pragma unroll
        for (int i = 0; i < 4; i++)
#pragma unroll
            for (int f = 0; f < 4; f++) {
                const int bb = f >> 1, jj = f & 1;
#pragma unroll
                for (int c = 0; c < 4; c++) {
                    const int colg = ng * 128 + warpN * 32 + bb * 16 + jj * 8 + tig * 2 + (c & 1);
                    const float h = tanh_fast(acc[i][f][c] + s_b0[colg]);
                    fa[i][c >> 1] = fmaf(h, s_w1[colg], fa[i][c >> 1]);
                }
            }
    }

    // ---- final reduce + scatter into s_F (once) ----
#pragma unroll
    for (int i = 0; i < 4; i++)
#pragma unroll
        for (int hh = 0; hh < 2; hh++) {
            fa[i][hh] += __shfl_xor_sync(0xffffffffu, fa[i][hh], 1);
            fa[i][hh] += __shfl_xor_sync(0xffffffffu, fa[i][hh], 2);
        }
    if (tig == 0) {
#pragma unroll
        for (int i = 0; i < 4; i++)
#pragma unroll
            for (int hh = 0; hh < 2; hh++) {
                const int m = warpM * 64 + i * 16 + hh * 8 + g;
                atomicAdd(&s_F[m], fa[i][hh]);
            }
    }

    __syncthreads();   // all warps' s_F contributions done
    if (tid < TILE_M) {
        if (row0 + tid < cnt) out[s_idx[tid]] = s_F[tid] + b1s;
    }
}

// ---------------- launch ----------------
extern "C" void kernel_launch(void* const* d_in, const int* in_sizes, int n_in,
                              void* d_out, int out_size) {
    const float* q  = (const float*)d_in[0];
    const int*   Z  = (const int*)d_in[1];
    const float* W0 = (const float*)d_in[2];
    const float* b0 = (const float*)d_in[3];
    const float* W1 = (const float*)d_in[4];
    const float* b1 = (const float*)d_in[5];
    float* out = (float*)d_out;
    int n = in_sizes[1];

    k_init_transpose<<<512, 256>>>(W0);
    k_scatter<<<(n + 255) / 256, 256>>>(Z, n);
    k_warm<<<128, 256>>>();

    cudaFuncSetAttribute(k_gemm, cudaFuncAttributeMaxDynamicSharedMemorySize, SMEM_BYTES);
    k_gemm<<<MAX_TILES, BLOCK, SMEM_BYTES>>>(q, b0, W1, b1, out);
}

// round 15
// speedup vs baseline: 2.1255x; 2.1255x over previous
#include <cuda_runtime.h>
#include <cuda_fp16.h>
#include <cstdint>

// ---------------- problem constants ----------------
#define N_ATOMS_MAX 131072
#define DQ      256
#define H1      512
#define NTYPE   4
#define TILE_M  128
#define MAX_TILES (N_ATOMS_MAX / TILE_M + NTYPE)  // 1028
#define BLOCK   256

// ---------------- smem layout (byte offsets) ----------------
// A: [blk16 0..7][grp 0..15][lane 0..31] x 16 B   (fragment-order, lane^(grp&7) swizzle)
// B: none — B fragments are loaded LDG->register from L2-resident g_W0H
#define B_OFF_F    0                    // s_F[128] floats
#define B_OFF_IDX  512                  // s_idx[128] ints
#define B_OFF_B0   1024                 // s_b0[512] floats
#define B_OFF_W1   3072                 // s_w1[512] floats
#define B_OFF_A    5120                 // 64 KB
#define SMEM_BYTES (B_OFF_A + 65536)    // 70656 B -> 2 CTAs / SM

// ---------------- device scratch ----------------
__device__ __half g_W0H[NTYPE * H1 * DQ];      // W0^T fp16, (chunk,group)-sliced fragment order
__device__ int    g_idx[NTYPE * N_ATOMS_MAX];  // per-type regions
__device__ int    g_cnt[NTYPE];
__device__ float  g_warm_sink;

// ---------------- helpers ----------------
static __device__ __forceinline__ float tanh_fast(float x) {
    float y;
    asm("tanh.approx.f32 %0, %1;" : "=f"(y) : "f"(x));
    return y;
}
static __device__ __forceinline__ uint32_t pack_h2(float lo, float hi) {
    uint32_t r;
    asm("cvt.rn.f16x2.f32 %0, %1, %2;" : "=r"(r) : "f"(hi), "f"(lo));
    return r;
}
static __device__ __forceinline__ void mma_f16(float* c, uint32_t a0, uint32_t a1,
                                               uint32_t a2, uint32_t a3,
                                               uint32_t b0, uint32_t b1) {
    asm volatile(
        "mma.sync.aligned.m16n8k16.row.col.f32.f16.f16.f32 "
        "{%0,%1,%2,%3}, {%4,%5,%6,%7}, {%8,%9}, {%0,%1,%2,%3};"
        : "+f"(c[0]), "+f"(c[1]), "+f"(c[2]), "+f"(c[3])
        : "r"(a0), "r"(a1), "r"(a2), "r"(a3), "r"(b0), "r"(b1));
}

// ---------------- prep 1: init counters + W0 transpose into sliced fragment-order ----
__global__ void k_init_transpose(const float* __restrict__ W0) {
    if (blockIdx.x == 0 && threadIdx.x < NTYPE) g_cnt[threadIdx.x] = 0;
    __shared__ float tile[32][33];
    const int bid = blockIdx.x;
    const int kx = bid & 7, jy = (bid >> 3) & 15, t = bid >> 7;
    const int k0 = kx * 32, j0 = jy * 32;
    const int x = threadIdx.x & 31, y0 = threadIdx.x >> 5;   // 32 x 8
#pragma unroll
    for (int dy = 0; dy < 32; dy += 8) {
        int k = k0 + y0 + dy, j = j0 + x;
        tile[y0 + dy][x] = W0[((size_t)t * DQ + k) * H1 + j];
    }
    __syncthreads();
#pragma unroll
    for (int dy = 0; dy < 32; dy += 8) {
        const int j = j0 + y0 + dy;      // H1 index (n)
        const int k = k0 + x;            // DQ index
        const int ng   = j >> 7;         // 128-col n-group
        const int blkn = (j >> 4) & 7;   // 16-col block within group
        const int gn   = blkn >> 1;      // warpN that reads this block
        const int bb   = blkn & 1;
        const int rb   = j & 15;
        const int jj = rb >> 3, g = rb & 7;
        const int kc = k >> 6;           // 64-k chunk
        const int p  = (k >> 4) & 3;     // k16 step within chunk
        const int ki = k & 15;
        const int tg = (ki >> 1) & 3;
        const int posq = ((ki >> 3) << 1) | (ki & 1);
        const int lane = g * 4 + tg;     // no swizzle: read by LDG
        const int ci = ng * 4 + kc;
        const int halfIdx = (((((ci * 4 + gn) * 2 + bb) * 4 + p) * 32 + lane) << 3) + jj * 4 + posq;
        g_W0H[(size_t)t * (H1 * DQ) + halfIdx] = __float2half_rn(tile[x][y0 + dy]);
    }
}

// ---------------- prep 2: scatter with block-aggregated atomics ----------------
__global__ void k_scatter(const int* __restrict__ Z, int n) {
    __shared__ int wcnt[8][NTYPE];
    __shared__ int wbase[8][NTYPE];
    __shared__ int blkbase[NTYPE];
    const int i = blockIdx.x * blockDim.x + threadIdx.x;
    const int lane = threadIdx.x & 31, w = threadIdx.x >> 5;
    int z = -1, rank = 0;
    if (i < n) {
        z = Z[i];
#pragma unroll
        for (int t = 0; t < NTYPE; t++) {
            unsigned m = __ballot_sync(0xffffffffu, z == t);
            if (lane == 0) wcnt[w][t] = __popc(m);
            if (z == t) rank = __popc(m & ((1u << lane) - 1u));
        }
    } else if (lane == 0) {
#pragma unroll
        for (int t = 0; t < NTYPE; t++) wcnt[w][t] = 0;
    }
    __syncthreads();
    if (threadIdx.x < NTYPE) {
        const int t = threadIdx.x;
        int s = 0;
#pragma unroll
        for (int w2 = 0; w2 < 8; w2++) { wbase[w2][t] = s; s += wcnt[w2][t]; }
        blkbase[t] = atomicAdd(&g_cnt[t], s);
    }
    __syncthreads();
    if (z >= 0) g_idx[z * N_ATOMS_MAX + blkbase[z] + wbase[w][z] + rank] = i;
}

// ---------------- prep 3: warm g_W0H into L2 (also keeps k_gemm as 4th launch) ----
__global__ void k_warm() {
    const float2* p = (const float2*)g_W0H;   // 512 KB = 65536 float2
    float acc = 0.0f;
    const int i0 = blockIdx.x * 256 + threadIdx.x;
    for (int i = i0; i < 65536; i += 128 * 256) {
        float2 v = p[i];
        acc += v.x + v.y;
    }
    if (acc == 12345.678f) g_warm_sink = acc;  // never true; defeats DCE
}

// ---------------- main fused GEMM + tanh + dot kernel ----------------
__global__ void __launch_bounds__(BLOCK, 2)
k_gemm(const float* __restrict__ q, const float* __restrict__ b0,
       const float* __restrict__ W1, const float* __restrict__ b1v,
       float* __restrict__ out) {
    extern __shared__ char smem[];
    const int tid = threadIdx.x;
    const int wid = tid >> 5, lane = tid & 31;
    const int g = lane >> 2, tig = lane & 3;
    const int warpM = wid & 1, warpN = wid >> 1;   // 2M x 4N; warp tile 64 rows x 32 cols
    // ---- tile table from g_cnt ----
    const int c0 = g_cnt[0], c1 = g_cnt[1], c2 = g_cnt[2], c3 = g_cnt[3];
    const int n0 = (c0 + TILE_M - 1) >> 7;
    const int n1 = (c1 + TILE_M - 1) >> 7;
    const int n2 = (c2 + TILE_M - 1) >> 7;
    const int bid = blockIdx.x;
    int t, lt, cnt;
    if (bid < n0)                { t = 0; lt = bid;                cnt = c0; }
    else if (bid < n0 + n1)      { t = 1; lt = bid - n0;           cnt = c1; }
    else if (bid < n0 + n1 + n2) { t = 2; lt = bid - n0 - n1;      cnt = c2; }
    else { t = 3; lt = bid - n0 - n1 - n2; cnt = c3;
           if (lt >= (c3 + TILE_M - 1) >> 7) return; }
    const int row0 = lt * TILE_M;

    float*  s_F   = (float*)(smem + B_OFF_F);
    int*    s_idx = (int*)(smem + B_OFF_IDX);
    float*  s_b0  = (float*)(smem + B_OFF_B0);
    float*  s_w1  = (float*)(smem + B_OFF_W1);
    char*   s_A   = smem + B_OFF_A;

    const __half* w0h = g_W0H + (size_t)t * (H1 * DQ);

    if (tid < TILE_M) {
        int r = row0 + tid;
        s_idx[tid] = g_idx[t * N_ATOMS_MAX + (r < cnt ? r : row0)];
        s_F[tid] = 0.0f;
    }
#pragma unroll
    for (int o = 0; o < 2; o++) {
        const int c = o * BLOCK + tid;
        s_b0[c] = b0[t * H1 + c];
        s_w1[c] = W1[t * H1 + c];
    }
    __syncthreads();   // s_idx visible

    // A gather: 128 rows x 16 k16-groups = 2048 tasks (8/thread)
#pragma unroll
    for (int o = 0; o < 8; o++) {
        const int lin = o * BLOCK + tid;
        const int grp = lin & 15, row = lin >> 4;
        const float* src = q + (size_t)s_idx[row] * DQ + grp * 16;
        float v[16];
#pragma unroll
        for (int s = 0; s < 4; s++) {
            const float4 f4 = *(const float4*)(src + s * 4);
            v[s * 4 + 0] = f4.x; v[s * 4 + 1] = f4.y;
            v[s * 4 + 2] = f4.z; v[s * 4 + 3] = f4.w;
        }
        const int blk = row >> 4, half = (row >> 3) & 1, gg = row & 7;
        char* dbase = s_A + ((blk * 16 + grp) << 9) + half * 8;
        const int sw = grp & 7;
#pragma unroll
        for (int tt = 0; tt < 4; tt++) {
            uint2 pr;
            pr.x = pack_h2(v[tt * 2],     v[tt * 2 + 1]);
            pr.y = pack_h2(v[tt * 2 + 8], v[tt * 2 + 9]);
            *(uint2*)(dbase + (((gg * 4 + tt) ^ sw) << 4)) = pr;
        }
    }
    __syncthreads();   // A tile visible to all warps; mainloop is barrier-free

    const float b1s = b1v[0];
    const char* As_base = s_A + warpM * 64 * 512;      // + (kc*4 + i*16 + p)*512 + swA
    const char* Bg_lane = (const char*)w0h + warpN * 4096 + lane * 16;

    // deferred per-row partials, accumulated across all 4 n-groups
    float fa[4][2];
#pragma unroll
    for (int i = 0; i < 4; i++) { fa[i][0] = 0.0f; fa[i][1] = 0.0f; }

    // B double buffer, continuous prefetch across ng boundaries (ss = ng*16 + s)
    uint4 Bb[2][2];
    Bb[0][0] = *(const uint4*)(Bg_lane);
    Bb[0][1] = *(const uint4*)(Bg_lane + 2048);

#pragma unroll 1
    for (int ng = 0; ng < 4; ng++) {            // 128-col n-groups
        const char* Bg = Bg_lane + ng * 65536;
        float acc[4][4][4];                     // [i: 16-row blk][f = bb*2+jj][c]
#pragma unroll
        for (int i = 0; i < 4; i++)
#pragma unroll
            for (int f = 0; f < 4; f++)
#pragma unroll
                for (int c = 0; c < 4; c++) acc[i][f][c] = 0.0f;

#pragma unroll
        for (int s = 0; s < 16; s++) {
            const int cur = s & 1, nxt = cur ^ 1;
            // prefetch B for global step ss+1 (static offsets relative to Bg)
            if (s < 15) {
                const int sn = s + 1;
                const char* Bn = Bg + (sn >> 2) * 16384 + (sn & 3) * 512;
                Bb[nxt][0] = *(const uint4*)(Bn);
                Bb[nxt][1] = *(const uint4*)(Bn + 2048);
            } else if (ng < 3) {                 // first step of next ng
                const char* Bn = Bg + 65536;
                Bb[nxt][0] = *(const uint4*)(Bn);
                Bb[nxt][1] = *(const uint4*)(Bn + 2048);
            }
            // A fragments for this step (smem; ptxas schedules ahead)
            const int kcn = s >> 2, pn = s & 3;
            const int swA = (lane ^ (((kcn & 1) << 2) | pn)) << 4;
            uint4 A[4];
#pragma unroll
            for (int i = 0; i < 4; i++)
                A[i] = *(const uint4*)(As_base + (kcn * 4 + i * 16 + pn) * 512 + swA);
            // A uint4: {a0, a2, a1, a3}; B uint4: {b0_j0, b1_j0, b0_j1, b1_j1}
#pragma unroll
            for (int i = 0; i < 4; i++) {
                mma_f16(acc[i][0], A[i].x, A[i].z, A[i].y, A[i].w, Bb[cur][0].x, Bb[cur][0].y);
                mma_f16(acc[i][1], A[i].x, A[i].z, A[i].y, A[i].w, Bb[cur][0].z, Bb[cur][0].w);
                mma_f16(acc[i][2], A[i].x, A[i].z, A[i].y, A[i].w, Bb[cur][1].x, Bb[cur][1].y);
                mma_f16(acc[i][3], A[i].x, A[i].z, A[i].y, A[i].w, Bb[cur][1].z, Bb[cur][1].w);
            }
        }

        // ---- per-ng: tanh(h + b0) * W1 into persistent fa (reduce deferred) ----
#pragma unroll
        for (int i = 0; i < 4; i++)
#pragma unroll
            for (int f = 0; f < 4; f++) {
                const int bb = f >> 1, jj = f & 1;
#pragma unroll
                for (int c = 0; c < 4; c++) {
                    const int colg = ng * 128 + warpN * 32 + bb * 16 + jj * 8 + tig * 2 + (c & 1);
                    const float h = tanh_fast(acc[i][f][c] + s_b0[colg]);
                    fa[i][c >> 1] = fmaf(h, s_w1[colg], fa[i][c >> 1]);
                }
            }
    }

    // ---- final reduce + scatter into s_F (once) ----
#pragma unroll
    for (int i = 0; i < 4; i++)
#pragma unroll
        for (int hh = 0; hh < 2; hh++) {
            fa[i][hh] += __shfl_xor_sync(0xffffffffu, fa[i][hh], 1);
            fa[i][hh] += __shfl_xor_sync(0xffffffffu, fa[i][hh], 2);
        }
    if (tig == 0) {
#pragma unroll
        for (int i = 0; i < 4; i++)
#pragma unroll
            for (int hh = 0; hh < 2; hh++) {
                const int m = warpM * 64 + i * 16 + hh * 8 + g;
                atomicAdd(&s_F[m], fa[i][hh]);
            }
    }

    __syncthreads();   // all warps' s_F contributions done
    if (tid < TILE_M) {
        if (row0 + tid < cnt) out[s_idx[tid]] = s_F[tid] + b1s;
    }
}

// ---------------- launch ----------------
extern "C" void kernel_launch(void* const* d_in, const int* in_sizes, int n_in,
                              void* d_out, int out_size) {
    const float* q  = (const float*)d_in[0];
    const int*   Z  = (const int*)d_in[1];
    const float* W0 = (const float*)d_in[2];
    const float* b0 = (const float*)d_in[3];
    const float* W1 = (const float*)d_in[4];
    const float* b1 = (const float*)d_in[5];
    float* out = (float*)d_out;
    int n = in_sizes[1];

    k_init_transpose<<<512, 256>>>(W0);
    k_scatter<<<(n + 255) / 256, 256>>>(Z, n);
    k_warm<<<128, 256>>>();

    cudaFuncSetAttribute(k_gemm, cudaFuncAttributeMaxDynamicSharedMemorySize, SMEM_BYTES);
    k_gemm<<<MAX_TILES, BLOCK, SMEM_BYTES>>>(q, b0, W1, b1, out);
}